// round 5
// baseline (speedup 1.0000x reference)
#include <cuda_runtime.h>
#include <cuda_bf16.h>
#include <math.h>
#include <stdint.h>

// Problem constants
#define Bq   1024
#define Kn   200
#define Dd   128
#define D2   256
#define G8   1024      // 8*D
#define STEPS 4

// ---------------- device scratch ----------------
__device__ float g_csum  [Bq * D2];
__device__ float g_support[Bq * Dd];
__device__ float g_hidden[Bq * D2];
__device__ float g_sg    [Bq * Dd];
__device__ float g_sgT   [Dd * Bq];
__device__ float g_gq    [Bq * G8];
__device__ float g_gates [Bq * G8];
__device__ float g_hr    [Bq * D2];
__device__ float g_c     [Bq * D2];
__device__ float g_hout  [Bq * Dd];
__device__ float g_logits[Bq * Bq];

// =================== helpers ===================
__device__ __forceinline__ uint32_t smem_u32(const void* p) {
    uint32_t a;
    asm("{ .reg .u64 t; cvta.to.shared.u64 t, %1; cvt.u32.u64 %0, t; }" : "=r"(a) : "l"(p));
    return a;
}

#define LDSM_X4(r0, r1, r2, r3, addr) \
    asm volatile("ldmatrix.sync.aligned.m8n8.x4.shared.b16 {%0,%1,%2,%3}, [%4];" \
        : "=r"(r0), "=r"(r1), "=r"(r2), "=r"(r3) : "r"(addr))

#define MMA_BF16(acc, a, bb0, bb1) \
    asm volatile("mma.sync.aligned.m16n8k16.row.col.f32.bf16.bf16.f32 " \
        "{%0,%1,%2,%3}, {%4,%5,%6,%7}, {%8,%9}, {%0,%1,%2,%3};" \
        : "+f"((acc)[0]), "+f"((acc)[1]), "+f"((acc)[2]), "+f"((acc)[3]) \
        : "r"((a)[0]), "r"((a)[1]), "r"((a)[2]), "r"((a)[3]), "r"(bb0), "r"(bb1))

// split two fp32 into bf16-hi pair + bf16-lo (residual) pair
__device__ __forceinline__ void split2(float x0, float x1, unsigned &h, unsigned &l) {
    __nv_bfloat162 hh = __float22bfloat162_rn(make_float2(x0, x1));
    float2 hf = __bfloat1622float2(hh);
    __nv_bfloat162 ll = __float22bfloat162_rn(make_float2(x0 - hf.x, x1 - hf.y));
    h = *reinterpret_cast<unsigned*>(&hh);
    l = *reinterpret_cast<unsigned*>(&ll);
}

// fused epilogue
__device__ __forceinline__ float epi(float x, int m, int n, int mode,
                                     const float* __restrict__ b1,
                                     const float* __restrict__ b2,
                                     const float* __restrict__ add, int ldadd) {
    if (mode == 1) return tanhf((x + 200.0f * b1[n]) * (1.0f / 1024.0f));
    if (mode == 2) return fmaxf(x + b1[n], 0.0f);
    if (mode == 3) return x + b1[n] + add[(size_t)m * ldadd + n];
    if (mode == 4) return x + b1[n] + b2[n];
    if (mode == 5) return x + add[(size_t)m * ldadd + n];
    return x;
}

// ========== HMMA TN GEMM: C = A(MxK) @ B(NxK)^T, fp32 via bf16x3 ==========
// CTA tile 32x32, 128 threads, warps 2x2 (each 16x16), K chunk 64, double-buffered.
// Optional aidx: A row m is read from A + aidx[m]*lda (fused gather).
// grid = (N/32, M/32)
#define LDS 72                      // bf16 per smem row (144B, ldmatrix conflict-free)
#define TILE_ELE (32 * LDS)         // 2304 bf16
#define TILE_B   (TILE_ELE * 2)     // 4608 bytes
#define BUF_B    (4 * TILE_B)       // 18432 bytes: Ah|Al|Bh|Bl
#define TG_SMEM  (2 * BUF_B)        // 36864

__global__ void __launch_bounds__(128)
tgemm(const float* __restrict__ A, int lda, const int* __restrict__ aidx,
      const float* __restrict__ B, int ldb,
      float* __restrict__ C, int ldc, int K,
      const float* __restrict__ b1, const float* __restrict__ b2,
      const float* __restrict__ add, int ldadd, int mode)
{
    extern __shared__ __nv_bfloat162 sm2[];
    const uint32_t sbase = smem_u32(sm2);

    const int tid  = threadIdx.x;
    const int lane = tid & 31;
    const int wid  = tid >> 5;
    const int wy   = wid >> 1;           // 0..1
    const int wx   = wid & 1;            // 0..1
    const int m0 = blockIdx.y * 32;
    const int n0 = blockIdx.x * 32;

    // loader indexing: row = tid/4 (0..31), col-quad = tid%4 (16 cols each)
    const int lr = tid >> 2;
    const int lc = (tid & 3) * 16;
    const int sIdx = lr * (LDS / 2) + lc / 2;     // bf162 index within a tile

    // ldmatrix byte offsets within a buffer
    const uint32_t aOff = (uint32_t)(((wy * 16 + (lane & 15)) * LDS + (lane >> 4) * 8) * 2);
    const int bg = lane >> 3;
    const uint32_t bOff = (uint32_t)(((wx * 16 + (bg >> 1) * 8 + (lane & 7)) * LDS + (bg & 1) * 8) * 2);

    float acc[2][4];
    #pragma unroll
    for (int j = 0; j < 2; j++)
        #pragma unroll
        for (int v = 0; v < 4; v++) acc[j][v] = 0.f;

    const int arow = m0 + lr;
    const float* Ap = (aidx ? A + (size_t)aidx[arow] * lda : A + (size_t)arow * lda) + lc;
    const float* Bp = B + (size_t)(n0 + lr) * ldb + lc;

    // prefetch chunk 0
    float4 pa[4], pb[4];
    #pragma unroll
    for (int j = 0; j < 4; j++) {
        pa[j] = *reinterpret_cast<const float4*>(Ap + j * 4);
        pb[j] = *reinterpret_cast<const float4*>(Bp + j * 4);
    }

    const int nchunks = K >> 6;
    for (int c = 0; c < nchunks; c++) {
        const int buf = c & 1;
        __nv_bfloat162* sAh = sm2 + buf * (BUF_B / 4);
        __nv_bfloat162* sAl = sAh + TILE_ELE / 2;
        __nv_bfloat162* sBh = sAl + TILE_ELE / 2;
        __nv_bfloat162* sBl = sBh + TILE_ELE / 2;

        #pragma unroll
        for (int j = 0; j < 4; j++) {
            unsigned h0, l0, h1, l1;
            split2(pa[j].x, pa[j].y, h0, l0);
            split2(pa[j].z, pa[j].w, h1, l1);
            sAh[sIdx + j * 2]     = *reinterpret_cast<__nv_bfloat162*>(&h0);
            sAh[sIdx + j * 2 + 1] = *reinterpret_cast<__nv_bfloat162*>(&h1);
            sAl[sIdx + j * 2]     = *reinterpret_cast<__nv_bfloat162*>(&l0);
            sAl[sIdx + j * 2 + 1] = *reinterpret_cast<__nv_bfloat162*>(&l1);
        }
        #pragma unroll
        for (int j = 0; j < 4; j++) {
            unsigned h0, l0, h1, l1;
            split2(pb[j].x, pb[j].y, h0, l0);
            split2(pb[j].z, pb[j].w, h1, l1);
            sBh[sIdx + j * 2]     = *reinterpret_cast<__nv_bfloat162*>(&h0);
            sBh[sIdx + j * 2 + 1] = *reinterpret_cast<__nv_bfloat162*>(&h1);
            sBl[sIdx + j * 2]     = *reinterpret_cast<__nv_bfloat162*>(&l0);
            sBl[sIdx + j * 2 + 1] = *reinterpret_cast<__nv_bfloat162*>(&l1);
        }

        if (c + 1 < nchunks) {
            const float* An = Ap + (c + 1) * 64;
            const float* Bn = Bp + (c + 1) * 64;
            #pragma unroll
            for (int j = 0; j < 4; j++) {
                pa[j] = *reinterpret_cast<const float4*>(An + j * 4);
                pb[j] = *reinterpret_cast<const float4*>(Bn + j * 4);
            }
        }
        __syncthreads();

        const uint32_t base = sbase + (uint32_t)buf * BUF_B;
        const uint32_t AhB = base, AlB = base + TILE_B, BhB = base + 2 * TILE_B, BlB = base + 3 * TILE_B;

        #pragma unroll
        for (int ks = 0; ks < 4; ks++) {
            uint32_t ah[4], al[4], bh[4], bl[4];
            const uint32_t kb = (uint32_t)(ks * 32);
            LDSM_X4(ah[0], ah[1], ah[2], ah[3], AhB + aOff + kb);
            LDSM_X4(al[0], al[1], al[2], al[3], AlB + aOff + kb);
            LDSM_X4(bh[0], bh[1], bh[2], bh[3], BhB + bOff + kb);
            LDSM_X4(bl[0], bl[1], bl[2], bl[3], BlB + bOff + kb);

            MMA_BF16(acc[0], ah, bh[0], bh[1]);
            MMA_BF16(acc[1], ah, bh[2], bh[3]);
            MMA_BF16(acc[0], ah, bl[0], bl[1]);
            MMA_BF16(acc[1], ah, bl[2], bl[3]);
            MMA_BF16(acc[0], al, bh[0], bh[1]);
            MMA_BF16(acc[1], al, bh[2], bh[3]);
        }
        // no trailing sync needed: buffer reuse is two iterations apart and the
        // per-iteration barrier orders compute(c) before store(c+2).
    }

    // ---- epilogue ----
    const int rbase = m0 + wy * 16 + (lane >> 2);
    const int cbase = n0 + wx * 16 + (lane & 3) * 2;
    #pragma unroll
    for (int ni = 0; ni < 2; ni++) {
        int cc = cbase + ni * 8;
        float2 v0, v1;
        v0.x = epi(acc[ni][0], rbase,     cc,     mode, b1, b2, add, ldadd);
        v0.y = epi(acc[ni][1], rbase,     cc + 1, mode, b1, b2, add, ldadd);
        v1.x = epi(acc[ni][2], rbase + 8, cc,     mode, b1, b2, add, ldadd);
        v1.y = epi(acc[ni][3], rbase + 8, cc + 1, mode, b1, b2, add, ldadd);
        *reinterpret_cast<float2*>(&C[(size_t)rbase * ldc + cc])       = v0;
        *reinterpret_cast<float2*>(&C[(size_t)(rbase + 8) * ldc + cc]) = v1;
    }
}

// =================== non-GEMM kernels ===================
__device__ __forceinline__ float sigm(float x) { return 1.0f / (1.0f + expf(-x)); }

__device__ __forceinline__ float bsum(float v, float* sm, int nw) {
    #pragma unroll
    for (int o = 16; o; o >>= 1) v += __shfl_xor_sync(0xffffffffu, v, o);
    int w = threadIdx.x >> 5;
    __syncthreads();
    if ((threadIdx.x & 31) == 0) sm[w] = v;
    __syncthreads();
    float r = 0.f;
    for (int i = 0; i < nw; i++) r += sm[i];
    return r;
}

__global__ __launch_bounds__(256) void gather_sum_kernel(
    const int* __restrict__ rel, const int* __restrict__ ent,
    const float* __restrict__ emb, float* __restrict__ csum)
{
    int b = blockIdx.x;
    int tid = threadIdx.x;
    int warp = tid >> 5, lane = tid & 31;

    __shared__ int sidx[2 * Kn];
    for (int i = tid; i < 2 * Kn; i += 256)
        sidx[i] = (i < Kn) ? rel[b * Kn + i] : ent[b * Kn + (i - Kn)];
    __syncthreads();

    int side = warp >> 2;
    int w    = warp & 3;
    const int* idxs = sidx + side * Kn;

    float4 acc = make_float4(0.f, 0.f, 0.f, 0.f);
    #pragma unroll 4
    for (int k = w; k < Kn; k += 4) {
        int row = idxs[k];
        float4 v = *reinterpret_cast<const float4*>(emb + (size_t)row * Dd + lane * 4);
        acc.x += v.x; acc.y += v.y; acc.z += v.z; acc.w += v.w;
    }

    __shared__ float4 red[8][32];
    red[warp][lane] = acc;
    __syncthreads();
    if ((warp & 3) == 0) {
        float4 s  = red[warp][lane];
        float4 s1 = red[warp + 1][lane];
        float4 s2 = red[warp + 2][lane];
        float4 s3 = red[warp + 3][lane];
        s.x += s1.x + s2.x + s3.x;
        s.y += s1.y + s2.y + s3.y;
        s.z += s1.z + s2.z + s3.z;
        s.w += s1.w + s2.w + s3.w;
        *reinterpret_cast<float4*>(csum + b * D2 + side * Dd + lane * 4) = s;
    }
}

// layernorm + fused transpose (writes sg in-place and sgT)
__global__ __launch_bounds__(128) void layernorm_kernel(float* __restrict__ Z,
                                                        float* __restrict__ ZT,
                                                        const float* __restrict__ a,
                                                        const float* __restrict__ b)
{
    __shared__ float sm[4];
    int row = blockIdx.x, t = threadIdx.x;
    float z = Z[row * Dd + t];
    float mu = bsum(z, sm, 4) * (1.0f / Dd);
    float d = z - mu;
    float var = bsum(d * d, sm, 4) * (1.0f / (Dd - 1));
    float sig = sqrtf(var);
    float v = d / (sig + 1e-3f) * a[t] + b[t];
    Z[row * Dd + t] = v;
    ZT[(size_t)t * Bq + row] = v;
}

// LSTM elementwise; gathers q row directly from emb via qry
__global__ __launch_bounds__(256) void lstm_ew_kernel(const float* __restrict__ gates,
                                                      const float* __restrict__ emb,
                                                      const int* __restrict__ qry,
                                                      float* __restrict__ c,
                                                      float* __restrict__ hout,
                                                      float* __restrict__ hr,
                                                      int first)
{
    int b = blockIdx.x, t = threadIdx.x;
    const float* g = gates + (size_t)b * G8;
    float ig = g[t];
    float fg = g[D2 + t];
    float gg = g[2 * D2 + t];
    float cprev = first ? 0.f : c[b * D2 + t];
    float cn = sigm(fg) * cprev + sigm(ig) * tanhf(gg);
    c[b * D2 + t] = cn;
    if (t < Dd) {
        float og = g[3 * D2 + t];
        float h  = sigm(og) * tanhf(cn);
        float ho = emb[(size_t)qry[b] * Dd + t] + h;
        hout[b * Dd + t] = ho;
        hr[b * D2 + t]   = ho;
    }
}

__global__ __launch_bounds__(256) void softmax_kernel(float* __restrict__ P)
{
    __shared__ float sm[8];
    __shared__ float ss[8];
    int row = blockIdx.x, t = threadIdx.x;
    float* p = P + (size_t)row * Bq;
    float4 v = *reinterpret_cast<const float4*>(p + t * 4);
    float m = fmaxf(fmaxf(v.x, v.y), fmaxf(v.z, v.w));
    #pragma unroll
    for (int o = 16; o; o >>= 1) m = fmaxf(m, __shfl_xor_sync(0xffffffffu, m, o));
    if ((t & 31) == 0) sm[t >> 5] = m;
    __syncthreads();
    float M = sm[0];
    #pragma unroll
    for (int i = 1; i < 8; i++) M = fmaxf(M, sm[i]);
    float e0 = expf(v.x - M), e1 = expf(v.y - M), e2 = expf(v.z - M), e3 = expf(v.w - M);
    float s = e0 + e1 + e2 + e3;
    #pragma unroll
    for (int o = 16; o; o >>= 1) s += __shfl_xor_sync(0xffffffffu, s, o);
    if ((t & 31) == 0) ss[t >> 5] = s;
    __syncthreads();
    float S = 0.f;
    #pragma unroll
    for (int i = 0; i < 8; i++) S += ss[i];
    float inv = 1.0f / S;
    *reinterpret_cast<float4*>(p + t * 4) = make_float4(e0 * inv, e1 * inv, e2 * inv, e3 * inv);
}

__global__ __launch_bounds__(128) void cosine_kernel(const float* __restrict__ H,
                                                     const float* __restrict__ G,
                                                     float* __restrict__ out)
{
    __shared__ float sm[4];
    int row = blockIdx.x, t = threadIdx.x;
    float h = H[row * Dd + t];
    float g = G[row * Dd + t];
    float s1 = bsum(h * g, sm, 4);
    float s2 = bsum(h * h, sm, 4);
    float s3 = bsum(g * g, sm, 4);
    if (t == 0) out[row] = s1 / sqrtf(s2 * s3);
}

// =================== launcher ===================
extern "C" void kernel_launch(void* const* d_in, const int* in_sizes, int n_in,
                              void* d_out, int out_size)
{
    const int*   rel = (const int*)d_in[0];
    const int*   ent = (const int*)d_in[1];
    const int*   qry = (const int*)d_in[2];
    const float* emb = (const float*)d_in[3];
    const float* Wg  = (const float*)d_in[4];
    const float* bg  = (const float*)d_in[5];
    const float* p1w = (const float*)d_in[6];
    const float* p1b = (const float*)d_in[7];
    const float* p2w = (const float*)d_in[8];
    const float* p2b = (const float*)d_in[9];
    const float* lna = (const float*)d_in[10];
    const float* lnb = (const float*)d_in[11];
    const float* wih = (const float*)d_in[12];
    const float* whh = (const float*)d_in[13];
    const float* bih = (const float*)d_in[14];
    const float* bhh = (const float*)d_in[15];
    float* out = (float*)d_out;

    float *csum, *support, *hidden, *sg, *sgT, *gq, *gates, *hr, *c, *hout, *logits;
    cudaGetSymbolAddress((void**)&csum,    g_csum);
    cudaGetSymbolAddress((void**)&support, g_support);
    cudaGetSymbolAddress((void**)&hidden,  g_hidden);
    cudaGetSymbolAddress((void**)&sg,      g_sg);
    cudaGetSymbolAddress((void**)&sgT,     g_sgT);
    cudaGetSymbolAddress((void**)&gq,      g_gq);
    cudaGetSymbolAddress((void**)&gates,   g_gates);
    cudaGetSymbolAddress((void**)&hr,      g_hr);
    cudaGetSymbolAddress((void**)&c,       g_c);
    cudaGetSymbolAddress((void**)&hout,    g_hout);
    cudaGetSymbolAddress((void**)&logits,  g_logits);

    cudaFuncSetAttribute(tgemm, cudaFuncAttributeMaxDynamicSharedMemorySize, TG_SMEM);

    // 1) neighbor gather-sum
    gather_sum_kernel<<<Bq, 256>>>(rel, ent, emb, csum);

    // 2) support = tanh((csum @ Wg^T + 200*bg) / 1024)
    tgemm<<<dim3(4, 32), 128, TG_SMEM>>>(csum, D2, nullptr, Wg, D2, support, Dd,
                                         D2, bg, nullptr, nullptr, 0, 1);
    // 3) hidden = relu(support @ p1w^T + p1b)
    tgemm<<<dim3(8, 32), 128, TG_SMEM>>>(support, Dd, nullptr, p1w, Dd, hidden, D2,
                                         Dd, p1b, nullptr, nullptr, 0, 2);
    // 4) sg = hidden @ p2w^T + p2b + support ; LN(+transpose) in-place
    tgemm<<<dim3(4, 32), 128, TG_SMEM>>>(hidden, D2, nullptr, p2w, D2, sg, Dd,
                                         D2, p2b, nullptr, support, Dd, 3);
    layernorm_kernel<<<Bq, 128>>>(sg, sgT, lna, lnb);

    // 5) gq = emb[qry] @ wih^T + bih + bhh (fused gather; first 896 gate cols)
    tgemm<<<dim3(28, 32), 128, TG_SMEM>>>(emb, Dd, qry, wih, Dd, gq, G8,
                                          Dd, bih, bhh, nullptr, 0, 4);

    // 6) LSTM + attention loop
    for (int s = 0; s < STEPS; s++) {
        const float* gsrc = gq;
        if (s > 0) {
            tgemm<<<dim3(28, 32), 128, TG_SMEM>>>(hr, D2, nullptr, whh, D2, gates, G8,
                                                  D2, nullptr, nullptr, gq, G8, 5);
            gsrc = gates;
        }
        lstm_ew_kernel<<<Bq, 256>>>(gsrc, emb, qry, c, hout, hr, s == 0 ? 1 : 0);

        // logits = hout @ sg^T ; softmax rows
        tgemm<<<dim3(32, 32), 128, TG_SMEM>>>(hout, Dd, nullptr, sg, Dd, logits, Bq,
                                              Dd, nullptr, nullptr, nullptr, 0, 0);
        softmax_kernel<<<Bq, 256>>>(logits);

        // r = P @ sg = P @ (sgT)^T : TN GEMM K=1024, write into hr[:,128:256]
        tgemm<<<dim3(4, 32), 128, TG_SMEM>>>(logits, Bq, nullptr, sgT, Bq, hr + Dd, D2,
                                             Bq, nullptr, nullptr, nullptr, 0, 0);
    }

    // 7) cosine similarity
    cosine_kernel<<<Bq, 128>>>(hout, sg, out);
}

// round 6
// speedup vs baseline: 1.2610x; 1.2610x over previous
#include <cuda_runtime.h>
#include <cuda_bf16.h>
#include <math.h>
#include <stdint.h>

// Problem constants
#define Bq   1024
#define Kn   200
#define Dd   128
#define D2   256
#define G8   1024      // 8*D
#define STEPS 4

// ---------------- device scratch ----------------
__device__ float g_csum  [Bq * D2];
__device__ float g_support[Bq * Dd];
__device__ float g_hidden[Bq * D2];
__device__ float g_sg    [Bq * Dd];
__device__ float g_sgT   [Dd * Bq];
__device__ float g_gq    [Bq * G8];
__device__ float g_gates [Bq * G8];
__device__ float g_hr    [Bq * D2];
__device__ float g_c     [Bq * D2];
__device__ float g_hout  [Bq * Dd];
__device__ float g_logits[Bq * Bq];
__device__ float g_part  [4 * Bq * D2];   // split-K partials (max: z=2 x 1024 x 256)
__device__ float g_m     [Bq];
__device__ float g_l     [Bq];

// =================== helpers ===================
__device__ __forceinline__ uint32_t smem_u32(const void* p) {
    uint32_t a;
    asm("{ .reg .u64 t; cvta.to.shared.u64 t, %1; cvt.u32.u64 %0, t; }" : "=r"(a) : "l"(p));
    return a;
}

#define LDSM_X4(r0, r1, r2, r3, addr) \
    asm volatile("ldmatrix.sync.aligned.m8n8.x4.shared.b16 {%0,%1,%2,%3}, [%4];" \
        : "=r"(r0), "=r"(r1), "=r"(r2), "=r"(r3) : "r"(addr))

#define MMA_BF16(acc, a, bb0, bb1) \
    asm volatile("mma.sync.aligned.m16n8k16.row.col.f32.bf16.bf16.f32 " \
        "{%0,%1,%2,%3}, {%4,%5,%6,%7}, {%8,%9}, {%0,%1,%2,%3};" \
        : "+f"((acc)[0]), "+f"((acc)[1]), "+f"((acc)[2]), "+f"((acc)[3]) \
        : "r"((a)[0]), "r"((a)[1]), "r"((a)[2]), "r"((a)[3]), "r"(bb0), "r"(bb1))

__device__ __forceinline__ void split2(float x0, float x1, unsigned &h, unsigned &l) {
    __nv_bfloat162 hh = __float22bfloat162_rn(make_float2(x0, x1));
    float2 hf = __bfloat1622float2(hh);
    __nv_bfloat162 ll = __float22bfloat162_rn(make_float2(x0 - hf.x, x1 - hf.y));
    h = *reinterpret_cast<unsigned*>(&hh);
    l = *reinterpret_cast<unsigned*>(&ll);
}

// fused epilogue (GEMM direct-output modes)
__device__ __forceinline__ float epi(float x, int m, int n, int mode,
                                     const float* __restrict__ b1,
                                     const float* __restrict__ b2,
                                     const float* __restrict__ add, int ldadd) {
    if (mode == 4) return x + b1[n] + b2[n];
    if (mode == 5) return x + add[(size_t)m * ldadd + n];
    return x;
}

// ========== HMMA TN GEMM: C = A(MxK) @ B(NxK)^T, fp32 via bf16x3 ==========
// CTA tile 64x64, 256 threads, warps 2x4 (each 32x16), K chunk 64, double-buffered,
// register prefetch. Optional aidx: A row gather. Optional aexp: A values -> exp(a-aexp[row]).
// grid = (N/64, M/64, zsplit); z chunk = [z*kchunk, (z+1)*kchunk), C += z*zstride
#define LDS 72
#define TILE_ELE (64 * LDS)
#define TILE_B   (TILE_ELE * 2)
#define BUF_B    (4 * TILE_B)
#define TG_SMEM  (2 * BUF_B)        // 73728

__global__ void __launch_bounds__(256)
tgemm(const float* __restrict__ A, int lda, const int* __restrict__ aidx,
      const float* __restrict__ aexp,
      const float* __restrict__ B, int ldb,
      float* __restrict__ C, int ldc,
      int kchunk, long zstride,
      const float* __restrict__ b1, const float* __restrict__ b2,
      const float* __restrict__ add, int ldadd, int mode)
{
    extern __shared__ __nv_bfloat162 sm2[];
    const uint32_t sbase = smem_u32(sm2);

    const int tid  = threadIdx.x;
    const int lane = tid & 31;
    const int wid  = tid >> 5;
    const int wy   = wid >> 2;
    const int wx   = wid & 3;
    const int m0 = blockIdx.y * 64;
    const int n0 = blockIdx.x * 64;
    const int kbeg = blockIdx.z * kchunk;
    C += (long)blockIdx.z * zstride;

    const int lr = tid >> 2;
    const int lc = (tid & 3) * 16;
    const int sIdx = lr * (LDS / 2) + lc / 2;

    const uint32_t aOff = (uint32_t)(((wy * 32 + (lane & 15)) * LDS + (lane >> 4) * 8) * 2);
    const int bg = lane >> 3;
    const uint32_t bOff = (uint32_t)(((wx * 16 + (bg >> 1) * 8 + (lane & 7)) * LDS + (bg & 1) * 8) * 2);

    float acc[2][2][4];
    #pragma unroll
    for (int i = 0; i < 2; i++)
        #pragma unroll
        for (int j = 0; j < 2; j++)
            #pragma unroll
            for (int v = 0; v < 4; v++) acc[i][j][v] = 0.f;

    const int arow = m0 + lr;
    const float* Ap = (aidx ? A + (size_t)aidx[arow] * lda : A + (size_t)arow * lda) + kbeg + lc;
    const float* Bp = B + (size_t)(n0 + lr) * ldb + kbeg + lc;
    const float mr = aexp ? aexp[arow] : 0.f;

    float4 pa[4], pb[4];
    #pragma unroll
    for (int j = 0; j < 4; j++) {
        pa[j] = *reinterpret_cast<const float4*>(Ap + j * 4);
        pb[j] = *reinterpret_cast<const float4*>(Bp + j * 4);
    }

    const int nchunks = kchunk >> 6;
    for (int c = 0; c < nchunks; c++) {
        const int buf = c & 1;
        __nv_bfloat162* sAh = sm2 + buf * (BUF_B / 4);
        __nv_bfloat162* sAl = sAh + TILE_ELE / 2;
        __nv_bfloat162* sBh = sAl + TILE_ELE / 2;
        __nv_bfloat162* sBl = sBh + TILE_ELE / 2;

        #pragma unroll
        for (int j = 0; j < 4; j++) {
            float4 v = pa[j];
            if (aexp) {
                v.x = __expf(v.x - mr); v.y = __expf(v.y - mr);
                v.z = __expf(v.z - mr); v.w = __expf(v.w - mr);
            }
            unsigned h0, l0, h1, l1;
            split2(v.x, v.y, h0, l0);
            split2(v.z, v.w, h1, l1);
            sAh[sIdx + j * 2]     = *reinterpret_cast<__nv_bfloat162*>(&h0);
            sAh[sIdx + j * 2 + 1] = *reinterpret_cast<__nv_bfloat162*>(&h1);
            sAl[sIdx + j * 2]     = *reinterpret_cast<__nv_bfloat162*>(&l0);
            sAl[sIdx + j * 2 + 1] = *reinterpret_cast<__nv_bfloat162*>(&l1);
        }
        #pragma unroll
        for (int j = 0; j < 4; j++) {
            unsigned h0, l0, h1, l1;
            split2(pb[j].x, pb[j].y, h0, l0);
            split2(pb[j].z, pb[j].w, h1, l1);
            sBh[sIdx + j * 2]     = *reinterpret_cast<__nv_bfloat162*>(&h0);
            sBh[sIdx + j * 2 + 1] = *reinterpret_cast<__nv_bfloat162*>(&h1);
            sBl[sIdx + j * 2]     = *reinterpret_cast<__nv_bfloat162*>(&l0);
            sBl[sIdx + j * 2 + 1] = *reinterpret_cast<__nv_bfloat162*>(&l1);
        }

        if (c + 1 < nchunks) {
            const float* An = Ap + (c + 1) * 64;
            const float* Bn = Bp + (c + 1) * 64;
            #pragma unroll
            for (int j = 0; j < 4; j++) {
                pa[j] = *reinterpret_cast<const float4*>(An + j * 4);
                pb[j] = *reinterpret_cast<const float4*>(Bn + j * 4);
            }
        }
        __syncthreads();

        const uint32_t base = sbase + (uint32_t)buf * BUF_B;
        const uint32_t AhB = base, AlB = base + TILE_B, BhB = base + 2 * TILE_B, BlB = base + 3 * TILE_B;

        #pragma unroll
        for (int ks = 0; ks < 4; ks++) {
            uint32_t ah0[4], ah1[4], al0[4], al1[4], bh[4], bl[4];
            const uint32_t kb = (uint32_t)(ks * 32);
            LDSM_X4(ah0[0], ah0[1], ah0[2], ah0[3], AhB + aOff + kb);
            LDSM_X4(ah1[0], ah1[1], ah1[2], ah1[3], AhB + aOff + kb + 16 * LDS * 2);
            LDSM_X4(al0[0], al0[1], al0[2], al0[3], AlB + aOff + kb);
            LDSM_X4(al1[0], al1[1], al1[2], al1[3], AlB + aOff + kb + 16 * LDS * 2);
            LDSM_X4(bh[0], bh[1], bh[2], bh[3], BhB + bOff + kb);
            LDSM_X4(bl[0], bl[1], bl[2], bl[3], BlB + bOff + kb);

            MMA_BF16(acc[0][0], ah0, bh[0], bh[1]);
            MMA_BF16(acc[0][1], ah0, bh[2], bh[3]);
            MMA_BF16(acc[1][0], ah1, bh[0], bh[1]);
            MMA_BF16(acc[1][1], ah1, bh[2], bh[3]);
            MMA_BF16(acc[0][0], ah0, bl[0], bl[1]);
            MMA_BF16(acc[0][1], ah0, bl[2], bl[3]);
            MMA_BF16(acc[1][0], ah1, bl[0], bl[1]);
            MMA_BF16(acc[1][1], ah1, bl[2], bl[3]);
            MMA_BF16(acc[0][0], al0, bh[0], bh[1]);
            MMA_BF16(acc[0][1], al0, bh[2], bh[3]);
            MMA_BF16(acc[1][0], al1, bh[0], bh[1]);
            MMA_BF16(acc[1][1], al1, bh[2], bh[3]);
        }
    }

    // ---- epilogue ----
    const int rbase = m0 + wy * 32 + (lane >> 2);
    const int cbase = n0 + wx * 16 + (lane & 3) * 2;
    #pragma unroll
    for (int mi = 0; mi < 2; mi++) {
        #pragma unroll
        for (int ni = 0; ni < 2; ni++) {
            int cc = cbase + ni * 8;
            int r0 = rbase + mi * 16;
            float2 v0, v1;
            v0.x = epi(acc[mi][ni][0], r0,     cc,     mode, b1, b2, add, ldadd);
            v0.y = epi(acc[mi][ni][1], r0,     cc + 1, mode, b1, b2, add, ldadd);
            v1.x = epi(acc[mi][ni][2], r0 + 8, cc,     mode, b1, b2, add, ldadd);
            v1.y = epi(acc[mi][ni][3], r0 + 8, cc + 1, mode, b1, b2, add, ldadd);
            *reinterpret_cast<float2*>(&C[(size_t)r0 * ldc + cc])       = v0;
            *reinterpret_cast<float2*>(&C[(size_t)(r0 + 8) * ldc + cc]) = v1;
        }
    }
}

// ====== split-K reduce + epilogue ======
// modes: 1 tanh((s+200*b1[n])/1024) | 2 relu(s+b1[n]) | 3 s+b1[n]+add[m][n] | 6 s/l[m]
__global__ __launch_bounds__(256) void reduce_epi(
    const float* __restrict__ part, int z, int MN, int N,
    float* __restrict__ C, int ldc,
    const float* __restrict__ b1, const float* __restrict__ add, int ldadd,
    const float* __restrict__ lrow, int mode)
{
    int i4 = (blockIdx.x * 256 + threadIdx.x) * 4;
    if (i4 >= MN) return;
    float4 s = *reinterpret_cast<const float4*>(part + i4);
    for (int zz = 1; zz < z; zz++) {
        float4 p = *reinterpret_cast<const float4*>(part + (size_t)zz * MN + i4);
        s.x += p.x; s.y += p.y; s.z += p.z; s.w += p.w;
    }
    int m = i4 / N, n = i4 % N;
    float v[4] = {s.x, s.y, s.z, s.w};
    #pragma unroll
    for (int j = 0; j < 4; j++) {
        if (mode == 1)      v[j] = tanhf((v[j] + 200.0f * b1[n + j]) * (1.0f / 1024.0f));
        else if (mode == 2) v[j] = fmaxf(v[j] + b1[n + j], 0.0f);
        else if (mode == 3) v[j] = v[j] + b1[n + j] + add[(size_t)m * ldadd + n + j];
        else if (mode == 6) v[j] = v[j] / lrow[m];
    }
    *reinterpret_cast<float4*>(&C[(size_t)m * ldc + n]) = make_float4(v[0], v[1], v[2], v[3]);
}

// =================== non-GEMM kernels ===================
__device__ __forceinline__ float sigm(float x) { return 1.0f / (1.0f + expf(-x)); }

__device__ __forceinline__ float bsum(float v, float* sm, int nw) {
    #pragma unroll
    for (int o = 16; o; o >>= 1) v += __shfl_xor_sync(0xffffffffu, v, o);
    int w = threadIdx.x >> 5;
    __syncthreads();
    if ((threadIdx.x & 31) == 0) sm[w] = v;
    __syncthreads();
    float r = 0.f;
    for (int i = 0; i < nw; i++) r += sm[i];
    return r;
}

__global__ __launch_bounds__(256) void gather_sum_kernel(
    const int* __restrict__ rel, const int* __restrict__ ent,
    const float* __restrict__ emb, float* __restrict__ csum)
{
    int b = blockIdx.x;
    int tid = threadIdx.x;
    int warp = tid >> 5, lane = tid & 31;

    __shared__ int sidx[2 * Kn];
    for (int i = tid; i < 2 * Kn; i += 256)
        sidx[i] = (i < Kn) ? rel[b * Kn + i] : ent[b * Kn + (i - Kn)];
    __syncthreads();

    int side = warp >> 2;
    int w    = warp & 3;
    const int* idxs = sidx + side * Kn;

    float4 acc = make_float4(0.f, 0.f, 0.f, 0.f);
    #pragma unroll 4
    for (int k = w; k < Kn; k += 4) {
        int row = idxs[k];
        float4 v = *reinterpret_cast<const float4*>(emb + (size_t)row * Dd + lane * 4);
        acc.x += v.x; acc.y += v.y; acc.z += v.z; acc.w += v.w;
    }

    __shared__ float4 red[8][32];
    red[warp][lane] = acc;
    __syncthreads();
    if ((warp & 3) == 0) {
        float4 s  = red[warp][lane];
        float4 s1 = red[warp + 1][lane];
        float4 s2 = red[warp + 2][lane];
        float4 s3 = red[warp + 3][lane];
        s.x += s1.x + s2.x + s3.x;
        s.y += s1.y + s2.y + s3.y;
        s.z += s1.z + s2.z + s3.z;
        s.w += s1.w + s2.w + s3.w;
        *reinterpret_cast<float4*>(csum + b * D2 + side * Dd + lane * 4) = s;
    }
}

// layernorm + fused transpose
__global__ __launch_bounds__(128) void layernorm_kernel(float* __restrict__ Z,
                                                        float* __restrict__ ZT,
                                                        const float* __restrict__ a,
                                                        const float* __restrict__ b)
{
    __shared__ float sm[4];
    int row = blockIdx.x, t = threadIdx.x;
    float z = Z[row * Dd + t];
    float mu = bsum(z, sm, 4) * (1.0f / Dd);
    float d = z - mu;
    float var = bsum(d * d, sm, 4) * (1.0f / (Dd - 1));
    float sig = sqrtf(var);
    float v = d / (sig + 1e-3f) * a[t] + b[t];
    Z[row * Dd + t] = v;
    ZT[(size_t)t * Bq + row] = v;
}

// LSTM elementwise; q gathered from emb via qry
__global__ __launch_bounds__(256) void lstm_ew_kernel(const float* __restrict__ gates,
                                                      const float* __restrict__ emb,
                                                      const int* __restrict__ qry,
                                                      float* __restrict__ c,
                                                      float* __restrict__ hout,
                                                      float* __restrict__ hr,
                                                      int first)
{
    int b = blockIdx.x, t = threadIdx.x;
    const float* g = gates + (size_t)b * G8;
    float ig = g[t];
    float fg = g[D2 + t];
    float gg = g[2 * D2 + t];
    float cprev = first ? 0.f : c[b * D2 + t];
    float cn = sigm(fg) * cprev + sigm(ig) * tanhf(gg);
    c[b * D2 + t] = cn;
    if (t < Dd) {
        float og = g[3 * D2 + t];
        float h  = sigm(og) * tanhf(cn);
        float ho = emb[(size_t)qry[b] * Dd + t] + h;
        hout[b * Dd + t] = ho;
        hr[b * D2 + t]   = ho;
    }
}

// per-row softmax stats: m = max, l = sum exp(x-m)  (no P write)
__global__ __launch_bounds__(256) void stats_kernel(const float* __restrict__ P,
                                                    float* __restrict__ m_arr,
                                                    float* __restrict__ l_arr)
{
    __shared__ float sm[8];
    __shared__ float ss[8];
    int row = blockIdx.x, t = threadIdx.x;
    const float* p = P + (size_t)row * Bq;
    float4 v = *reinterpret_cast<const float4*>(p + t * 4);
    float m = fmaxf(fmaxf(v.x, v.y), fmaxf(v.z, v.w));
    #pragma unroll
    for (int o = 16; o; o >>= 1) m = fmaxf(m, __shfl_xor_sync(0xffffffffu, m, o));
    if ((t & 31) == 0) sm[t >> 5] = m;
    __syncthreads();
    float M = sm[0];
    #pragma unroll
    for (int i = 1; i < 8; i++) M = fmaxf(M, sm[i]);
    float s = __expf(v.x - M) + __expf(v.y - M) + __expf(v.z - M) + __expf(v.w - M);
    #pragma unroll
    for (int o = 16; o; o >>= 1) s += __shfl_xor_sync(0xffffffffu, s, o);
    if ((t & 31) == 0) ss[t >> 5] = s;
    __syncthreads();
    if (t == 0) {
        float S = 0.f;
        #pragma unroll
        for (int i = 0; i < 8; i++) S += ss[i];
        m_arr[row] = M;
        l_arr[row] = S;
    }
}

__global__ __launch_bounds__(128) void cosine_kernel(const float* __restrict__ H,
                                                     const float* __restrict__ G,
                                                     float* __restrict__ out)
{
    __shared__ float sm[4];
    int row = blockIdx.x, t = threadIdx.x;
    float h = H[row * Dd + t];
    float g = G[row * Dd + t];
    float s1 = bsum(h * g, sm, 4);
    float s2 = bsum(h * h, sm, 4);
    float s3 = bsum(g * g, sm, 4);
    if (t == 0) out[row] = s1 / sqrtf(s2 * s3);
}

// =================== launcher ===================
extern "C" void kernel_launch(void* const* d_in, const int* in_sizes, int n_in,
                              void* d_out, int out_size)
{
    const int*   rel = (const int*)d_in[0];
    const int*   ent = (const int*)d_in[1];
    const int*   qry = (const int*)d_in[2];
    const float* emb = (const float*)d_in[3];
    const float* Wg  = (const float*)d_in[4];
    const float* bg  = (const float*)d_in[5];
    const float* p1w = (const float*)d_in[6];
    const float* p1b = (const float*)d_in[7];
    const float* p2w = (const float*)d_in[8];
    const float* p2b = (const float*)d_in[9];
    const float* lna = (const float*)d_in[10];
    const float* lnb = (const float*)d_in[11];
    const float* wih = (const float*)d_in[12];
    const float* whh = (const float*)d_in[13];
    const float* bih = (const float*)d_in[14];
    const float* bhh = (const float*)d_in[15];
    float* out = (float*)d_out;

    float *csum, *support, *hidden, *sg, *sgT, *gq, *gates, *hr, *c, *hout, *logits, *part, *mrr, *lrr;
    cudaGetSymbolAddress((void**)&csum,    g_csum);
    cudaGetSymbolAddress((void**)&support, g_support);
    cudaGetSymbolAddress((void**)&hidden,  g_hidden);
    cudaGetSymbolAddress((void**)&sg,      g_sg);
    cudaGetSymbolAddress((void**)&sgT,     g_sgT);
    cudaGetSymbolAddress((void**)&gq,      g_gq);
    cudaGetSymbolAddress((void**)&gates,   g_gates);
    cudaGetSymbolAddress((void**)&hr,      g_hr);
    cudaGetSymbolAddress((void**)&c,       g_c);
    cudaGetSymbolAddress((void**)&hout,    g_hout);
    cudaGetSymbolAddress((void**)&logits,  g_logits);
    cudaGetSymbolAddress((void**)&part,    g_part);
    cudaGetSymbolAddress((void**)&mrr,     g_m);
    cudaGetSymbolAddress((void**)&lrr,     g_l);

    cudaFuncSetAttribute(tgemm, cudaFuncAttributeMaxDynamicSharedMemorySize, TG_SMEM);

    // 1) neighbor gather-sum
    gather_sum_kernel<<<Bq, 256>>>(rel, ent, emb, csum);

    // 2) support = tanh((csum @ Wg^T + 200*bg)/1024): split-K z=4 + reduce
    tgemm<<<dim3(2, 16, 4), 256, TG_SMEM>>>(csum, D2, nullptr, nullptr, Wg, D2,
                                            part, Dd, 64, (long)Bq * Dd,
                                            nullptr, nullptr, nullptr, 0, 0);
    reduce_epi<<<Bq * Dd / 1024, 256>>>(part, 4, Bq * Dd, Dd, support, Dd,
                                        bg, nullptr, 0, nullptr, 1);

    // 3) hidden = relu(support @ p1w^T + p1b): split-K z=2 + reduce
    tgemm<<<dim3(4, 16, 2), 256, TG_SMEM>>>(support, Dd, nullptr, nullptr, p1w, Dd,
                                            part, D2, 64, (long)Bq * D2,
                                            nullptr, nullptr, nullptr, 0, 0);
    reduce_epi<<<Bq * D2 / 1024, 256>>>(part, 2, Bq * D2, D2, hidden, D2,
                                        p1b, nullptr, 0, nullptr, 2);

    // 4) sg = hidden @ p2w^T + p2b + support: split-K z=4 + reduce; LN(+T)
    tgemm<<<dim3(2, 16, 4), 256, TG_SMEM>>>(hidden, D2, nullptr, nullptr, p2w, D2,
                                            part, Dd, 64, (long)Bq * Dd,
                                            nullptr, nullptr, nullptr, 0, 0);
    reduce_epi<<<Bq * Dd / 1024, 256>>>(part, 4, Bq * Dd, Dd, sg, Dd,
                                        p2b, support, Dd, nullptr, 3);
    layernorm_kernel<<<Bq, 128>>>(sg, sgT, lna, lnb);

    // 5) gq = emb[qry] @ wih^T + bih + bhh (fused gather; 896 gate cols)
    tgemm<<<dim3(14, 16, 1), 256, TG_SMEM>>>(emb, Dd, qry, nullptr, wih, Dd,
                                             gq, G8, Dd, 0,
                                             bih, bhh, nullptr, 0, 4);

    // 6) LSTM + attention loop
    for (int s = 0; s < STEPS; s++) {
        const float* gsrc = gq;
        if (s > 0) {
            tgemm<<<dim3(14, 16, 1), 256, TG_SMEM>>>(hr, D2, nullptr, nullptr, whh, D2,
                                                     gates, G8, D2, 0,
                                                     nullptr, nullptr, gq, G8, 5);
            gsrc = gates;
        }
        lstm_ew_kernel<<<Bq, 256>>>(gsrc, emb, qry, c, hout, hr, s == 0 ? 1 : 0);

        // logits = hout @ sg^T
        tgemm<<<dim3(16, 16, 1), 256, TG_SMEM>>>(hout, Dd, nullptr, nullptr, sg, Dd,
                                                 logits, Bq, Dd, 0,
                                                 nullptr, nullptr, nullptr, 0, 0);
        // row stats (max, sumexp)
        stats_kernel<<<Bq, 256>>>(logits, mrr, lrr);

        // r = exp(logits - m) @ sg / l : split-K z=4 with fused exp on A, reduce divides
        tgemm<<<dim3(2, 16, 4), 256, TG_SMEM>>>(logits, Bq, nullptr, mrr, sgT, Bq,
                                                part, Dd, 256, (long)Bq * Dd,
                                                nullptr, nullptr, nullptr, 0, 0);
        reduce_epi<<<Bq * Dd / 1024, 256>>>(part, 4, Bq * Dd, Dd, hr + Dd, D2,
                                            nullptr, nullptr, 0, lrr, 6);
    }

    // 7) cosine similarity
    cosine_kernel<<<Bq, 128>>>(hout, sg, out);
}

// round 7
// speedup vs baseline: 1.4895x; 1.1812x over previous
#include <cuda_runtime.h>
#include <cuda_bf16.h>
#include <math.h>
#include <stdint.h>

// Problem constants
#define Bq   1024
#define Kn   200
#define Dd   128
#define D2   256
#define G8   1024      // 8*D
#define STEPS 4
#define KVSPLIT 8

// ---------------- device scratch ----------------
__device__ float g_csum  [Bq * D2];
__device__ float g_support[Bq * Dd];
__device__ float g_hidden[Bq * D2];
__device__ float g_sg    [Bq * Dd];
__device__ float g_sgT   [Dd * Bq];
__device__ float g_gq    [Bq * G8];
__device__ float g_gates [Bq * G8];
__device__ float g_hr    [Bq * D2];
__device__ float g_c     [Bq * D2];
__device__ float g_hout  [Bq * Dd];
__device__ float g_part  [4 * Bq * D2];     // split-K partials / flash partials (4MB)
__device__ float g_m     [KVSPLIT * Bq];
__device__ float g_l     [KVSPLIT * Bq];

// =================== helpers ===================
__device__ __forceinline__ uint32_t smem_u32(const void* p) {
    uint32_t a;
    asm("{ .reg .u64 t; cvta.to.shared.u64 t, %1; cvt.u32.u64 %0, t; }" : "=r"(a) : "l"(p));
    return a;
}

#define LDSM_X4(r0, r1, r2, r3, addr) \
    asm volatile("ldmatrix.sync.aligned.m8n8.x4.shared.b16 {%0,%1,%2,%3}, [%4];" \
        : "=r"(r0), "=r"(r1), "=r"(r2), "=r"(r3) : "r"(addr))

#define MMA_BF16(acc, a, bb0, bb1) \
    asm volatile("mma.sync.aligned.m16n8k16.row.col.f32.bf16.bf16.f32 " \
        "{%0,%1,%2,%3}, {%4,%5,%6,%7}, {%8,%9}, {%0,%1,%2,%3};" \
        : "+f"((acc)[0]), "+f"((acc)[1]), "+f"((acc)[2]), "+f"((acc)[3]) \
        : "r"((a)[0]), "r"((a)[1]), "r"((a)[2]), "r"((a)[3]), "r"(bb0), "r"(bb1))

__device__ __forceinline__ void split2(float x0, float x1, unsigned &h, unsigned &l) {
    __nv_bfloat162 hh = __float22bfloat162_rn(make_float2(x0, x1));
    float2 hf = __bfloat1622float2(hh);
    __nv_bfloat162 ll = __float22bfloat162_rn(make_float2(x0 - hf.x, x1 - hf.y));
    h = *reinterpret_cast<unsigned*>(&hh);
    l = *reinterpret_cast<unsigned*>(&ll);
}

#define LDS 72
#define TILE_ELE (64 * LDS)
#define TILE_B   (TILE_ELE * 2)     // 9216
#define BUF_B    (4 * TILE_B)
#define TG_SMEM  (2 * BUF_B)

// one K=64 chunk of split-3 MMAs into acc[2][2][4] (warp tile 32x32 over hi/lo pairs)
__device__ __forceinline__ void mma_chunk(
    uint32_t AhB, uint32_t AlB, uint32_t BhB, uint32_t BlB,
    uint32_t aOff, uint32_t bOff, float acc[2][2][4])
{
    #pragma unroll
    for (int ks = 0; ks < 4; ks++) {
        uint32_t ah0[4], ah1[4], al0[4], al1[4], bh[4], bl[4];
        const uint32_t kb = (uint32_t)(ks * 32);
        LDSM_X4(ah0[0], ah0[1], ah0[2], ah0[3], AhB + aOff + kb);
        LDSM_X4(ah1[0], ah1[1], ah1[2], ah1[3], AhB + aOff + kb + 16 * LDS * 2);
        LDSM_X4(al0[0], al0[1], al0[2], al0[3], AlB + aOff + kb);
        LDSM_X4(al1[0], al1[1], al1[2], al1[3], AlB + aOff + kb + 16 * LDS * 2);
        LDSM_X4(bh[0], bh[1], bh[2], bh[3], BhB + bOff + kb);
        LDSM_X4(bl[0], bl[1], bl[2], bl[3], BlB + bOff + kb);

        MMA_BF16(acc[0][0], ah0, bh[0], bh[1]);
        MMA_BF16(acc[0][1], ah0, bh[2], bh[3]);
        MMA_BF16(acc[1][0], ah1, bh[0], bh[1]);
        MMA_BF16(acc[1][1], ah1, bh[2], bh[3]);
        MMA_BF16(acc[0][0], ah0, bl[0], bl[1]);
        MMA_BF16(acc[0][1], ah0, bl[2], bl[3]);
        MMA_BF16(acc[1][0], ah1, bl[0], bl[1]);
        MMA_BF16(acc[1][1], ah1, bl[2], bl[3]);
        MMA_BF16(acc[0][0], al0, bh[0], bh[1]);
        MMA_BF16(acc[0][1], al0, bh[2], bh[3]);
        MMA_BF16(acc[1][0], al1, bh[0], bh[1]);
        MMA_BF16(acc[1][1], al1, bh[2], bh[3]);
    }
}

// stage a 64x64 fp32 tile -> bf16 hi/lo smem (A/B layout, LDS=72)
__device__ __forceinline__ void stage64(char* fsm, uint32_t offh, uint32_t offl,
                                        const float* __restrict__ src, int sIdx) {
    __nv_bfloat162* dh = reinterpret_cast<__nv_bfloat162*>(fsm + offh);
    __nv_bfloat162* dl = reinterpret_cast<__nv_bfloat162*>(fsm + offl);
    #pragma unroll
    for (int j = 0; j < 4; j++) {
        float4 v = *reinterpret_cast<const float4*>(src + j * 4);
        unsigned h0, l0, h1, l1;
        split2(v.x, v.y, h0, l0);
        split2(v.z, v.w, h1, l1);
        dh[sIdx + j * 2]     = *reinterpret_cast<__nv_bfloat162*>(&h0);
        dh[sIdx + j * 2 + 1] = *reinterpret_cast<__nv_bfloat162*>(&h1);
        dl[sIdx + j * 2]     = *reinterpret_cast<__nv_bfloat162*>(&l0);
        dl[sIdx + j * 2 + 1] = *reinterpret_cast<__nv_bfloat162*>(&l1);
    }
}

// fused epilogue (GEMM direct-output modes)
__device__ __forceinline__ float epi(float x, int m, int n, int mode,
                                     const float* __restrict__ b1,
                                     const float* __restrict__ b2,
                                     const float* __restrict__ add, int ldadd) {
    if (mode == 4) return x + b1[n] + b2[n];
    if (mode == 5) return x + add[(size_t)m * ldadd + n];
    return x;
}

// ========== HMMA TN GEMM (R6 engine, unchanged) ==========
__global__ void __launch_bounds__(256)
tgemm(const float* __restrict__ A, int lda, const int* __restrict__ aidx,
      const float* __restrict__ B, int ldb,
      float* __restrict__ C, int ldc,
      int kchunk, long zstride,
      const float* __restrict__ b1, const float* __restrict__ b2,
      const float* __restrict__ add, int ldadd, int mode)
{
    extern __shared__ __nv_bfloat162 sm2[];
    const uint32_t sbase = smem_u32(sm2);

    const int tid  = threadIdx.x;
    const int lane = tid & 31;
    const int wid  = tid >> 5;
    const int wy   = wid >> 2;
    const int wx   = wid & 3;
    const int m0 = blockIdx.y * 64;
    const int n0 = blockIdx.x * 64;
    const int kbeg = blockIdx.z * kchunk;
    C += (long)blockIdx.z * zstride;

    const int lr = tid >> 2;
    const int lc = (tid & 3) * 16;
    const int sIdx = lr * (LDS / 2) + lc / 2;

    const uint32_t aOff = (uint32_t)(((wy * 32 + (lane & 15)) * LDS + (lane >> 4) * 8) * 2);
    const int bg = lane >> 3;
    const uint32_t bOff = (uint32_t)(((wx * 16 + (bg >> 1) * 8 + (lane & 7)) * LDS + (bg & 1) * 8) * 2);

    float acc[2][2][4];
    #pragma unroll
    for (int i = 0; i < 2; i++)
        #pragma unroll
        for (int j = 0; j < 2; j++)
            #pragma unroll
            for (int v = 0; v < 4; v++) acc[i][j][v] = 0.f;

    const int arow = m0 + lr;
    const float* Ap = (aidx ? A + (size_t)aidx[arow] * lda : A + (size_t)arow * lda) + kbeg + lc;
    const float* Bp = B + (size_t)(n0 + lr) * ldb + kbeg + lc;

    float4 pa[4], pb[4];
    #pragma unroll
    for (int j = 0; j < 4; j++) {
        pa[j] = *reinterpret_cast<const float4*>(Ap + j * 4);
        pb[j] = *reinterpret_cast<const float4*>(Bp + j * 4);
    }

    const int nchunks = kchunk >> 6;
    for (int c = 0; c < nchunks; c++) {
        const int buf = c & 1;
        __nv_bfloat162* sAh = sm2 + buf * (BUF_B / 4);
        __nv_bfloat162* sAl = sAh + TILE_ELE / 2;
        __nv_bfloat162* sBh = sAl + TILE_ELE / 2;
        __nv_bfloat162* sBl = sBh + TILE_ELE / 2;

        #pragma unroll
        for (int j = 0; j < 4; j++) {
            unsigned h0, l0, h1, l1;
            split2(pa[j].x, pa[j].y, h0, l0);
            split2(pa[j].z, pa[j].w, h1, l1);
            sAh[sIdx + j * 2]     = *reinterpret_cast<__nv_bfloat162*>(&h0);
            sAh[sIdx + j * 2 + 1] = *reinterpret_cast<__nv_bfloat162*>(&h1);
            sAl[sIdx + j * 2]     = *reinterpret_cast<__nv_bfloat162*>(&l0);
            sAl[sIdx + j * 2 + 1] = *reinterpret_cast<__nv_bfloat162*>(&l1);
        }
        #pragma unroll
        for (int j = 0; j < 4; j++) {
            unsigned h0, l0, h1, l1;
            split2(pb[j].x, pb[j].y, h0, l0);
            split2(pb[j].z, pb[j].w, h1, l1);
            sBh[sIdx + j * 2]     = *reinterpret_cast<__nv_bfloat162*>(&h0);
            sBh[sIdx + j * 2 + 1] = *reinterpret_cast<__nv_bfloat162*>(&h1);
            sBl[sIdx + j * 2]     = *reinterpret_cast<__nv_bfloat162*>(&l0);
            sBl[sIdx + j * 2 + 1] = *reinterpret_cast<__nv_bfloat162*>(&l1);
        }

        if (c + 1 < nchunks) {
            const float* An = Ap + (c + 1) * 64;
            const float* Bn = Bp + (c + 1) * 64;
            #pragma unroll
            for (int j = 0; j < 4; j++) {
                pa[j] = *reinterpret_cast<const float4*>(An + j * 4);
                pb[j] = *reinterpret_cast<const float4*>(Bn + j * 4);
            }
        }
        __syncthreads();

        const uint32_t base = sbase + (uint32_t)buf * BUF_B;
        mma_chunk(base, base + TILE_B, base + 2 * TILE_B, base + 3 * TILE_B,
                  aOff, bOff, acc);
    }

    const int rbase = m0 + wy * 32 + (lane >> 2);
    const int cbase = n0 + wx * 16 + (lane & 3) * 2;
    #pragma unroll
    for (int mi = 0; mi < 2; mi++) {
        #pragma unroll
        for (int ni = 0; ni < 2; ni++) {
            int cc = cbase + ni * 8;
            int r0 = rbase + mi * 16;
            float2 v0, v1;
            v0.x = epi(acc[mi][ni][0], r0,     cc,     mode, b1, b2, add, ldadd);
            v0.y = epi(acc[mi][ni][1], r0,     cc + 1, mode, b1, b2, add, ldadd);
            v1.x = epi(acc[mi][ni][2], r0 + 8, cc,     mode, b1, b2, add, ldadd);
            v1.y = epi(acc[mi][ni][3], r0 + 8, cc + 1, mode, b1, b2, add, ldadd);
            *reinterpret_cast<float2*>(&C[(size_t)r0 * ldc + cc])       = v0;
            *reinterpret_cast<float2*>(&C[(size_t)(r0 + 8) * ldc + cc]) = v1;
        }
    }
}

// ========== flash attention: r = softmax(hout @ sg^T) @ sg, partial per kv-split ======
// grid (16 qtiles, KVSPLIT). CTA: 64 q rows, 128 keys (2 tiles of 64), online softmax.
#define FQ(ch)  ((uint32_t)((ch) * 18432))
#define FQL(ch) (FQ(ch) + 9216)
#define FK(ch)  ((uint32_t)(36864 + (ch) * 18432))
#define FKL(ch) (FK(ch) + 9216)
#define FV(nb)  ((uint32_t)(73728 + (nb) * 18432))
#define FVL(nb) (FV(nb) + 9216)
#define FPH 110592u
#define FPL 119808u
#define FS  129024u
#define FSC 145408u
#define FL_SMEM 145664

__global__ void __launch_bounds__(256)
flash_kernel(const float* __restrict__ hout, const float* __restrict__ sg,
             const float* __restrict__ sgT,
             float* __restrict__ part, float* __restrict__ msg, float* __restrict__ lsg)
{
    extern __shared__ char fsm[];
    const uint32_t sb = smem_u32(fsm);
    const int tid = threadIdx.x, lane = tid & 31, wid = tid >> 5;
    const int wy = wid >> 2, wx = wid & 3;
    const int m0 = blockIdx.x * 64;
    const int kv = blockIdx.y;
    const int lr = tid >> 2, lc = (tid & 3) * 16;
    const int sIdx = lr * (LDS / 2) + lc / 2;
    const uint32_t aOff = (uint32_t)(((wy * 32 + (lane & 15)) * LDS + (lane >> 4) * 8) * 2);
    const int bg = lane >> 3;
    const uint32_t bOff = (uint32_t)(((wx * 16 + (bg >> 1) * 8 + (lane & 7)) * LDS + (bg & 1) * 8) * 2);
    const int rbase = wy * 32 + (lane >> 2);
    const int cbase = wx * 16 + (lane & 3) * 2;

    // stage q tile once (2 K-chunks)
    stage64(fsm, FQ(0), FQL(0), hout + (size_t)(m0 + lr) * Dd + lc, sIdx);
    stage64(fsm, FQ(1), FQL(1), hout + (size_t)(m0 + lr) * Dd + 64 + lc, sIdx);

    const int srow = tid >> 2, seg = tid & 3;
    float mOld = -1e30f, lOld = 0.f;

    float oacc[2][2][2][4];   // [nb][mi][ni][v]
    #pragma unroll
    for (int a = 0; a < 2; a++)
        #pragma unroll
        for (int b = 0; b < 2; b++)
            #pragma unroll
            for (int cdx = 0; cdx < 2; cdx++)
                #pragma unroll
                for (int v = 0; v < 4; v++) oacc[a][b][cdx][v] = 0.f;

    for (int t = 0; t < 2; t++) {
        const int kbeg = kv * 128 + t * 64;
        // stage K (keys x 128 dims, 2 chunks) and V (dims x keys from sgT, 2 n-blocks)
        stage64(fsm, FK(0), FKL(0), sg + (size_t)(kbeg + lr) * Dd + lc, sIdx);
        stage64(fsm, FK(1), FKL(1), sg + (size_t)(kbeg + lr) * Dd + 64 + lc, sIdx);
        stage64(fsm, FV(0), FVL(0), sgT + (size_t)lr * Bq + kbeg + lc, sIdx);
        stage64(fsm, FV(1), FVL(1), sgT + (size_t)(64 + lr) * Bq + kbeg + lc, sIdx);
        __syncthreads();

        // S = q @ k^T (64x64)
        float sacc[2][2][4];
        #pragma unroll
        for (int i = 0; i < 2; i++)
            #pragma unroll
            for (int j = 0; j < 2; j++)
                #pragma unroll
                for (int v = 0; v < 4; v++) sacc[i][j][v] = 0.f;
        mma_chunk(sb + FQ(0), sb + FQL(0), sb + FK(0), sb + FKL(0), aOff, bOff, sacc);
        mma_chunk(sb + FQ(1), sb + FQL(1), sb + FK(1), sb + FKL(1), aOff, bOff, sacc);

        float* S = reinterpret_cast<float*>(fsm + FS);
        #pragma unroll
        for (int mi = 0; mi < 2; mi++)
            #pragma unroll
            for (int ni = 0; ni < 2; ni++) {
                int r0 = rbase + mi * 16, cc = cbase + ni * 8;
                S[r0 * 64 + cc]           = sacc[mi][ni][0];
                S[r0 * 64 + cc + 1]       = sacc[mi][ni][1];
                S[(r0 + 8) * 64 + cc]     = sacc[mi][ni][2];
                S[(r0 + 8) * 64 + cc + 1] = sacc[mi][ni][3];
            }
        __syncthreads();

        // online softmax stats: 4 threads per row, 16 cols each
        float e[16];
        const float* Srow = reinterpret_cast<float*>(fsm + FS) + srow * 64 + seg * 16;
        float mx = -1e30f;
        #pragma unroll
        for (int j = 0; j < 16; j++) { e[j] = Srow[j]; mx = fmaxf(mx, e[j]); }
        mx = fmaxf(mx, __shfl_xor_sync(0xffffffffu, mx, 1));
        mx = fmaxf(mx, __shfl_xor_sync(0xffffffffu, mx, 2));
        float mNew = fmaxf(mOld, mx);
        float sum = 0.f;
        #pragma unroll
        for (int j = 0; j < 16; j++) { e[j] = __expf(e[j] - mNew); sum += e[j]; }
        sum += __shfl_xor_sync(0xffffffffu, sum, 1);
        sum += __shfl_xor_sync(0xffffffffu, sum, 2);
        float scale = __expf(mOld - mNew);
        lOld = lOld * scale + sum;
        mOld = mNew;
        if (seg == 0) reinterpret_cast<float*>(fsm + FSC)[srow] = scale;
        // stage P (unnormalized) as bf16 hi/lo
        {
            __nv_bfloat162* Ph = reinterpret_cast<__nv_bfloat162*>(fsm + FPH);
            __nv_bfloat162* Pl = reinterpret_cast<__nv_bfloat162*>(fsm + FPL);
            int pIdx = srow * (LDS / 2) + seg * 8;
            #pragma unroll
            for (int j = 0; j < 8; j++) {
                unsigned h, l;
                split2(e[2 * j], e[2 * j + 1], h, l);
                Ph[pIdx + j] = *reinterpret_cast<__nv_bfloat162*>(&h);
                Pl[pIdx + j] = *reinterpret_cast<__nv_bfloat162*>(&l);
            }
        }
        __syncthreads();

        // rescale running output accumulators
        const float* SC = reinterpret_cast<float*>(fsm + FSC);
        float sc[4] = { SC[rbase], SC[rbase + 8], SC[rbase + 16], SC[rbase + 24] };
        #pragma unroll
        for (int nb = 0; nb < 2; nb++)
            #pragma unroll
            for (int mi = 0; mi < 2; mi++)
                #pragma unroll
                for (int ni = 0; ni < 2; ni++) {
                    oacc[nb][mi][ni][0] *= sc[mi * 2];
                    oacc[nb][mi][ni][1] *= sc[mi * 2];
                    oacc[nb][mi][ni][2] *= sc[mi * 2 + 1];
                    oacc[nb][mi][ni][3] *= sc[mi * 2 + 1];
                }

        // PV: out += P @ V  (two 64-dim n-blocks)
        mma_chunk(sb + FPH, sb + FPL, sb + FV(0), sb + FVL(0), aOff, bOff, oacc[0]);
        mma_chunk(sb + FPH, sb + FPL, sb + FV(1), sb + FVL(1), aOff, bOff, oacc[1]);
        __syncthreads();
    }

    if (seg == 0) {
        msg[kv * Bq + m0 + srow] = mOld;
        lsg[kv * Bq + m0 + srow] = lOld;
    }
    float* dst = part + ((size_t)kv * Bq + m0) * Dd;
    #pragma unroll
    for (int nb = 0; nb < 2; nb++)
        #pragma unroll
        for (int mi = 0; mi < 2; mi++)
            #pragma unroll
            for (int ni = 0; ni < 2; ni++) {
                int r0 = rbase + mi * 16, cc = nb * 64 + cbase + ni * 8;
                *reinterpret_cast<float2*>(&dst[(size_t)r0 * Dd + cc]) =
                    make_float2(oacc[nb][mi][ni][0], oacc[nb][mi][ni][1]);
                *reinterpret_cast<float2*>(&dst[(size_t)(r0 + 8) * Dd + cc]) =
                    make_float2(oacc[nb][mi][ni][2], oacc[nb][mi][ni][3]);
            }
}

// combine kv-split partials -> hr[:,128:256]
__global__ __launch_bounds__(128) void combine_kernel(
    const float* __restrict__ part, const float* __restrict__ msg,
    const float* __restrict__ lsg, float* __restrict__ hr)
{
    int r = blockIdx.x, d = threadIdx.x;
    float mstar = -1e30f;
    #pragma unroll
    for (int i = 0; i < KVSPLIT; i++) mstar = fmaxf(mstar, msg[i * Bq + r]);
    float lstar = 0.f, acc = 0.f;
    #pragma unroll
    for (int i = 0; i < KVSPLIT; i++) {
        float w = __expf(msg[i * Bq + r] - mstar);
        lstar += lsg[i * Bq + r] * w;
        acc   += part[((size_t)i * Bq + r) * Dd + d] * w;
    }
    hr[r * D2 + Dd + d] = acc / lstar;
}

// ====== split-K reduce + epilogue (prologue GEMMs) ======
__global__ __launch_bounds__(256) void reduce_epi(
    const float* __restrict__ part, int z, int MN, int N,
    float* __restrict__ C, int ldc,
    const float* __restrict__ b1, const float* __restrict__ add, int ldadd, int mode)
{
    int i4 = (blockIdx.x * 256 + threadIdx.x) * 4;
    if (i4 >= MN) return;
    float4 s = *reinterpret_cast<const float4*>(part + i4);
    for (int zz = 1; zz < z; zz++) {
        float4 p = *reinterpret_cast<const float4*>(part + (size_t)zz * MN + i4);
        s.x += p.x; s.y += p.y; s.z += p.z; s.w += p.w;
    }
    int m = i4 / N, n = i4 % N;
    float v[4] = {s.x, s.y, s.z, s.w};
    #pragma unroll
    for (int j = 0; j < 4; j++) {
        if (mode == 1)      v[j] = tanhf((v[j] + 200.0f * b1[n + j]) * (1.0f / 1024.0f));
        else if (mode == 2) v[j] = fmaxf(v[j] + b1[n + j], 0.0f);
        else if (mode == 3) v[j] = v[j] + b1[n + j] + add[(size_t)m * ldadd + n + j];
    }
    *reinterpret_cast<float4*>(&C[(size_t)m * ldc + n]) = make_float4(v[0], v[1], v[2], v[3]);
}

// =================== non-GEMM kernels ===================
__device__ __forceinline__ float sigm(float x) { return 1.0f / (1.0f + expf(-x)); }

__device__ __forceinline__ float bsum(float v, float* sm, int nw) {
    #pragma unroll
    for (int o = 16; o; o >>= 1) v += __shfl_xor_sync(0xffffffffu, v, o);
    int w = threadIdx.x >> 5;
    __syncthreads();
    if ((threadIdx.x & 31) == 0) sm[w] = v;
    __syncthreads();
    float r = 0.f;
    for (int i = 0; i < nw; i++) r += sm[i];
    return r;
}

__global__ __launch_bounds__(256) void gather_sum_kernel(
    const int* __restrict__ rel, const int* __restrict__ ent,
    const float* __restrict__ emb, float* __restrict__ csum)
{
    int b = blockIdx.x;
    int tid = threadIdx.x;
    int warp = tid >> 5, lane = tid & 31;

    __shared__ int sidx[2 * Kn];
    for (int i = tid; i < 2 * Kn; i += 256)
        sidx[i] = (i < Kn) ? rel[b * Kn + i] : ent[b * Kn + (i - Kn)];
    __syncthreads();

    int side = warp >> 2;
    int w    = warp & 3;
    const int* idxs = sidx + side * Kn;

    float4 acc = make_float4(0.f, 0.f, 0.f, 0.f);
    #pragma unroll 4
    for (int k = w; k < Kn; k += 4) {
        int row = idxs[k];
        float4 v = *reinterpret_cast<const float4*>(emb + (size_t)row * Dd + lane * 4);
        acc.x += v.x; acc.y += v.y; acc.z += v.z; acc.w += v.w;
    }

    __shared__ float4 red[8][32];
    red[warp][lane] = acc;
    __syncthreads();
    if ((warp & 3) == 0) {
        float4 s  = red[warp][lane];
        float4 s1 = red[warp + 1][lane];
        float4 s2 = red[warp + 2][lane];
        float4 s3 = red[warp + 3][lane];
        s.x += s1.x + s2.x + s3.x;
        s.y += s1.y + s2.y + s3.y;
        s.z += s1.z + s2.z + s3.z;
        s.w += s1.w + s2.w + s3.w;
        *reinterpret_cast<float4*>(csum + b * D2 + side * Dd + lane * 4) = s;
    }
}

__global__ __launch_bounds__(128) void layernorm_kernel(float* __restrict__ Z,
                                                        float* __restrict__ ZT,
                                                        const float* __restrict__ a,
                                                        const float* __restrict__ b)
{
    __shared__ float sm[4];
    int row = blockIdx.x, t = threadIdx.x;
    float z = Z[row * Dd + t];
    float mu = bsum(z, sm, 4) * (1.0f / Dd);
    float d = z - mu;
    float var = bsum(d * d, sm, 4) * (1.0f / (Dd - 1));
    float sig = sqrtf(var);
    float v = d / (sig + 1e-3f) * a[t] + b[t];
    Z[row * Dd + t] = v;
    ZT[(size_t)t * Bq + row] = v;
}

__global__ __launch_bounds__(256) void lstm_ew_kernel(const float* __restrict__ gates,
                                                      const float* __restrict__ emb,
                                                      const int* __restrict__ qry,
                                                      float* __restrict__ c,
                                                      float* __restrict__ hout,
                                                      float* __restrict__ hr,
                                                      int first)
{
    int b = blockIdx.x, t = threadIdx.x;
    const float* g = gates + (size_t)b * G8;
    float ig = g[t];
    float fg = g[D2 + t];
    float gg = g[2 * D2 + t];
    float cprev = first ? 0.f : c[b * D2 + t];
    float cn = sigm(fg) * cprev + sigm(ig) * tanhf(gg);
    c[b * D2 + t] = cn;
    if (t < Dd) {
        float og = g[3 * D2 + t];
        float h  = sigm(og) * tanhf(cn);
        float ho = emb[(size_t)qry[b] * Dd + t] + h;
        hout[b * Dd + t] = ho;
        hr[b * D2 + t]   = ho;
    }
}

__global__ __launch_bounds__(128) void cosine_kernel(const float* __restrict__ H,
                                                     const float* __restrict__ G,
                                                     float* __restrict__ out)
{
    __shared__ float sm[4];
    int row = blockIdx.x, t = threadIdx.x;
    float h = H[row * Dd + t];
    float g = G[row * Dd + t];
    float s1 = bsum(h * g, sm, 4);
    float s2 = bsum(h * h, sm, 4);
    float s3 = bsum(g * g, sm, 4);
    if (t == 0) out[row] = s1 / sqrtf(s2 * s3);
}

// =================== launcher ===================
extern "C" void kernel_launch(void* const* d_in, const int* in_sizes, int n_in,
                              void* d_out, int out_size)
{
    const int*   rel = (const int*)d_in[0];
    const int*   ent = (const int*)d_in[1];
    const int*   qry = (const int*)d_in[2];
    const float* emb = (const float*)d_in[3];
    const float* Wg  = (const float*)d_in[4];
    const float* bg  = (const float*)d_in[5];
    const float* p1w = (const float*)d_in[6];
    const float* p1b = (const float*)d_in[7];
    const float* p2w = (const float*)d_in[8];
    const float* p2b = (const float*)d_in[9];
    const float* lna = (const float*)d_in[10];
    const float* lnb = (const float*)d_in[11];
    const float* wih = (const float*)d_in[12];
    const float* whh = (const float*)d_in[13];
    const float* bih = (const float*)d_in[14];
    const float* bhh = (const float*)d_in[15];
    float* out = (float*)d_out;

    float *csum, *support, *hidden, *sg, *sgT, *gq, *gates, *hr, *c, *hout, *part, *mrr, *lrr;
    cudaGetSymbolAddress((void**)&csum,    g_csum);
    cudaGetSymbolAddress((void**)&support, g_support);
    cudaGetSymbolAddress((void**)&hidden,  g_hidden);
    cudaGetSymbolAddress((void**)&sg,      g_sg);
    cudaGetSymbolAddress((void**)&sgT,     g_sgT);
    cudaGetSymbolAddress((void**)&gq,      g_gq);
    cudaGetSymbolAddress((void**)&gates,   g_gates);
    cudaGetSymbolAddress((void**)&hr,      g_hr);
    cudaGetSymbolAddress((void**)&c,       g_c);
    cudaGetSymbolAddress((void**)&hout,    g_hout);
    cudaGetSymbolAddress((void**)&part,    g_part);
    cudaGetSymbolAddress((void**)&mrr,     g_m);
    cudaGetSymbolAddress((void**)&lrr,     g_l);

    cudaFuncSetAttribute(tgemm, cudaFuncAttributeMaxDynamicSharedMemorySize, TG_SMEM);
    cudaFuncSetAttribute(flash_kernel, cudaFuncAttributeMaxDynamicSharedMemorySize, FL_SMEM);

    // 1) neighbor gather-sum
    gather_sum_kernel<<<Bq, 256>>>(rel, ent, emb, csum);

    // 2) support = tanh((csum @ Wg^T + 200*bg)/1024): split-K z=4 + reduce
    tgemm<<<dim3(2, 16, 4), 256, TG_SMEM>>>(csum, D2, nullptr, Wg, D2,
                                            part, Dd, 64, (long)Bq * Dd,
                                            nullptr, nullptr, nullptr, 0, 0);
    reduce_epi<<<Bq * Dd / 1024, 256>>>(part, 4, Bq * Dd, Dd, support, Dd,
                                        bg, nullptr, 0, 1);

    // 3) hidden = relu(support @ p1w^T + p1b): split-K z=2 + reduce
    tgemm<<<dim3(4, 16, 2), 256, TG_SMEM>>>(support, Dd, nullptr, p1w, Dd,
                                            part, D2, 64, (long)Bq * D2,
                                            nullptr, nullptr, nullptr, 0, 0);
    reduce_epi<<<Bq * D2 / 1024, 256>>>(part, 2, Bq * D2, D2, hidden, D2,
                                        p1b, nullptr, 0, 2);

    // 4) sg = hidden @ p2w^T + p2b + support: split-K z=4 + reduce; LN(+T)
    tgemm<<<dim3(2, 16, 4), 256, TG_SMEM>>>(hidden, D2, nullptr, p2w, D2,
                                            part, Dd, 64, (long)Bq * Dd,
                                            nullptr, nullptr, nullptr, 0, 0);
    reduce_epi<<<Bq * Dd / 1024, 256>>>(part, 4, Bq * Dd, Dd, sg, Dd,
                                        p2b, support, Dd, 3);
    layernorm_kernel<<<Bq, 128>>>(sg, sgT, lna, lnb);

    // 5) gq = emb[qry] @ wih^T + bih + bhh (fused gather; 896 gate cols)
    tgemm<<<dim3(14, 16, 1), 256, TG_SMEM>>>(emb, Dd, qry, wih, Dd,
                                             gq, G8, Dd, 0,
                                             bih, bhh, nullptr, 0, 4);

    // 6) LSTM + flash-attention loop
    for (int s = 0; s < STEPS; s++) {
        const float* gsrc = gq;
        if (s > 0) {
            tgemm<<<dim3(14, 16, 1), 256, TG_SMEM>>>(hr, D2, nullptr, whh, D2,
                                                     gates, G8, D2, 0,
                                                     nullptr, nullptr, gq, G8, 5);
            gsrc = gates;
        }
        lstm_ew_kernel<<<Bq, 256>>>(gsrc, emb, qry, c, hout, hr, s == 0 ? 1 : 0);

        flash_kernel<<<dim3(16, KVSPLIT), 256, FL_SMEM>>>(hout, sg, sgT, part, mrr, lrr);
        combine_kernel<<<Bq, 128>>>(part, mrr, lrr, hr);
    }

    // 7) cosine similarity
    cosine_kernel<<<Bq, 128>>>(hout, sg, out);
}